// round 5
// baseline (speedup 1.0000x reference)
#include <cuda_runtime.h>

#define E_NUM 8192
#define D 64
#define S1_BLOCKS 592
#define EVB 32                      // events per block (stage-2 kernel)
#define EV_BLOCKS (E_NUM / EVB)     // 256

// ---------------- scratch (no allocs allowed) ----------------
// Contiguous region zeroed by one cudaMemsetAsync per replay.
__device__ float g_zero[2 * E_NUM + D + E_NUM * D];
#define g_P      (g_zero)                    // [E_NUM] segsum of max(x,0)
#define g_M      (g_zero + E_NUM)            // [E_NUM] segsum of max(-x,0)
#define g_gsum   (g_zero + 2 * E_NUM)        // [D]
#define g_pooled (g_zero + 2 * E_NUM + D)    // [E_NUM*D] generic-path pooled

__device__ float g_u[D], g_v[D];    // r1w0^T cp, r1w0^T cm (fast path)
__device__ int   g_flag;            // 1 => phi1 biases nonzero -> generic path
__device__ int   g_cnt;             // last-block ticket (self-resetting)

// packed f32x2 fma: d = a*b + d   (FFMA2 — only reachable via PTX)
__device__ __forceinline__ void ffma2(unsigned long long& d,
                                      unsigned long long a,
                                      unsigned long long b)
{
    asm("fma.rn.f32x2 %0, %1, %2, %0;" : "+l"(d) : "l"(a), "l"(b));
}

// ---------------- K1: stage-1 phi + segment pooling (+ prep fused) ----------------
__global__ void __launch_bounds__(256) k_stage1(
    const float* __restrict__ x, const int* __restrict__ seg, int n,
    const float* __restrict__ w0, const float* __restrict__ b0,
    const float* __restrict__ W1, const float* __restrict__ b1,
    const float* __restrict__ r1w0)
{
    const int tid = threadIdx.x;
    __shared__ float scp[D], scm[D];

    // per-block bias check
    int nz = 0;
    if (tid < D) nz = (b0[tid] != 0.f) || (b1[tid] != 0.f);
    const int anyb = __syncthreads_or(nz);

    // block 0 publishes flag and u,v for the events kernel
    if (blockIdx.x == 0) {
        if (tid == 0) g_flag = anyb;
        if (tid < D) {
            float vp = 0.f, vn = 0.f;
            #pragma unroll
            for (int j = 0; j < D; j++) {
                float w   = w0[j];
                float col = W1[j * D + tid];
                vp += fmaxf(w, 0.f)  * col;
                vn += fmaxf(-w, 0.f) * col;
            }
            scp[tid] = fmaxf(vp, 0.f);
            scm[tid] = fmaxf(vn, 0.f);
        }
        __syncthreads();
        if (tid < D) {
            float u = 0.f, v = 0.f;
            #pragma unroll
            for (int j = 0; j < D; j++) {
                float w = r1w0[j * D + tid];
                u += scp[j] * w;
                v += scm[j] * w;
            }
            g_u[tid] = u;
            g_v[tid] = v;
        }
    }

    if (!anyb) {
        // ---- fast path: two scalar segment sums, HBM-bound ----
        const int lane   = tid & 31;
        const int warp   = (blockIdx.x * blockDim.x + tid) >> 5;
        const int nwarps = (gridDim.x * blockDim.x) >> 5;
        const int G      = n >> 2;
        const int gpw    = (G + nwarps - 1) / nwarps;

        const long long gbase = (long long)warp * gpw;
        const long long gend0 = gbase + gpw;
        const long long gend  = gend0 < (long long)G ? gend0 : (long long)G;

        const float4* x4 = (const float4*)x;
        const int4*   s4 = (const int4*)seg;

        int   cur = -1;
        float aP = 0.f, aM = 0.f;

        for (long long g = gbase + lane; g < gend; g += 32) {
            float4 xv = x4[g];
            int4   sv = s4[g];
            int   ss[4] = {sv.x, sv.y, sv.z, sv.w};
            float xs[4] = {xv.x, xv.y, xv.z, xv.w};
            #pragma unroll
            for (int u = 0; u < 4; u++) {
                int s = ss[u];
                if (s != cur) {
                    if (cur >= 0) { atomicAdd(&g_P[cur], aP); atomicAdd(&g_M[cur], aM); }
                    cur = s; aP = 0.f; aM = 0.f;
                }
                aP += fmaxf(xs[u],  0.f);
                aM += fmaxf(-xs[u], 0.f);
            }
        }
        if (cur >= 0) { atomicAdd(&g_P[cur], aP); atomicAdd(&g_M[cur], aM); }

        if (warp == 0 && lane == 0) {
            for (int i = G * 4; i < n; i++) {
                float xv = x[i]; int s = seg[i];
                atomicAdd(&g_P[s], fmaxf(xv,  0.f));
                atomicAdd(&g_M[s], fmaxf(-xv, 0.f));
            }
        }
    } else {
        // ---- generic fallback (never taken for this problem's inputs) ----
        __shared__ float sw0[D], sb0[D], sW1[D * D], sb1[D];
        for (int i = tid; i < D; i += blockDim.x) {
            sw0[i] = w0[i]; sb0[i] = b0[i]; sb1[i] = b1[i];
        }
        for (int i = tid; i < D * D; i += blockDim.x) sW1[i] = W1[i];
        __syncthreads();

        const int stride = gridDim.x * blockDim.x;
        for (int i = blockIdx.x * blockDim.x + tid; i < n; i += stride) {
            float xv = x[i];
            int   e  = seg[i];
            float h1[D];
            #pragma unroll
            for (int j = 0; j < D; j++) h1[j] = fmaxf(xv * sw0[j] + sb0[j], 0.f);
            #pragma unroll 2
            for (int k = 0; k < D; k++) {
                float acc = sb1[k];
                #pragma unroll
                for (int j = 0; j < D; j++) acc += h1[j] * sW1[j * D + k];
                atomicAdd(&g_pooled[e * D + k], fmaxf(acc, 0.f));
            }
        }
    }
}

// ---------------- K2: fused event MLP (f32x2 packed) + global sum + final ----------------
#define TS 34   // tile row stride in floats (8B-aligned pairs, bank-rotated rows)

__global__ void __launch_bounds__(256, 2) k_events_final(
    const float* __restrict__ r1w0, const float* __restrict__ r1b0,
    const float* __restrict__ r1w1, const float* __restrict__ r1b1,
    const float* __restrict__ o1w,  const float* __restrict__ o1b,
    const float* __restrict__ p2w0, const float* __restrict__ p2b0,
    const float* __restrict__ p2w1, const float* __restrict__ p2b1,
    const float* __restrict__ r2w0, const float* __restrict__ r2b0,
    const float* __restrict__ r2w1, const float* __restrict__ r2b1,
    const float* __restrict__ o2w,  const float* __restrict__ o2b,
    float* __restrict__ out)
{
    __shared__ float2 shWd[D * D];      // weights duplicated (w,w)
    __shared__ float2 shBd[D];          // biases duplicated
    __shared__ float  tile[D * TS];     // transposed: [feat][event], EVB events
    __shared__ float  sP[EVB], sM[EVB];
    __shared__ float  sf0[D], sf1[D], sf2[D];
    __shared__ int    s_last;

    const int tid  = threadIdx.x;
    const int e0   = blockIdx.x * EVB;
    const int flag = g_flag;

    const int kq = tid >> 4;        // 0..15 -> 4-feature group
    const int ep = tid & 15;        // 0..15 -> event pair
    const int kb = kq * 4;

    const float* Ws[5];
    const float* Bs[5];
    int NL;

    if (!flag) {
        // layer 1 folded analytically; remaining 4 GEMM layers
        Ws[0] = r1w1; Bs[0] = r1b1;
        Ws[1] = o1w;  Bs[1] = o1b;
        Ws[2] = p2w0; Bs[2] = p2b0;
        Ws[3] = p2w1; Bs[3] = p2b1;
        NL = 4;

        if (tid < EVB)      sP[tid]       = g_P[e0 + tid];
        else if (tid < 2*EVB) sM[tid-EVB] = g_M[e0 + tid - EVB];
        __syncthreads();

        // h1 = relu(P*u + M*v + r1b0), written transposed
        #pragma unroll
        for (int t = 0; t < 4; t++) {
            int k = kb + t;
            float u = g_u[k], v = g_v[k], b = r1b0[k];
            float h0 = fmaxf(sP[2*ep]   * u + sM[2*ep]   * v + b, 0.f);
            float h1 = fmaxf(sP[2*ep+1] * u + sM[2*ep+1] * v + b, 0.f);
            *(float2*)&tile[k * TS + 2 * ep] = make_float2(h0, h1);
        }
    } else {
        Ws[0] = r1w0; Bs[0] = r1b0;
        Ws[1] = r1w1; Bs[1] = r1b1;
        Ws[2] = o1w;  Bs[2] = o1b;
        Ws[3] = p2w0; Bs[3] = p2b0;
        Ws[4] = p2w1; Bs[4] = p2b1;
        NL = 5;
        for (int i = tid; i < D * EVB; i += 256) {
            int j = i >> 5, e = i & (EVB - 1);
            tile[j * TS + e] = g_pooled[(e0 + e) * D + j];
        }
    }

    for (int L = 0; L < NL; L++) {
        // load duplicated weights + biases
        const float* W = Ws[L];
        #pragma unroll
        for (int s = 0; s < 16; s++) {
            int i = tid + s * 256;
            float w = W[i];
            shWd[i] = make_float2(w, w);
        }
        if (tid < D) {
            float b = Bs[L][tid];
            shBd[tid] = make_float2(b, b);
        }
        __syncthreads();   // weights ready + tile writes (init/store) done

        unsigned long long acc0 = *(unsigned long long*)&shBd[kb + 0];
        unsigned long long acc1 = *(unsigned long long*)&shBd[kb + 1];
        unsigned long long acc2 = *(unsigned long long*)&shBd[kb + 2];
        unsigned long long acc3 = *(unsigned long long*)&shBd[kb + 3];

        #pragma unroll 16
        for (int j = 0; j < D; j++) {
            unsigned long long ap =
                *(const unsigned long long*)&tile[j * TS + 2 * ep];
            ulonglong2 wA = *(const ulonglong2*)&shWd[j * D + kb];
            ulonglong2 wB = *(const ulonglong2*)&shWd[j * D + kb + 2];
            ffma2(acc0, ap, wA.x);
            ffma2(acc1, ap, wA.y);
            ffma2(acc2, ap, wB.x);
            ffma2(acc3, ap, wB.y);
        }
        __syncthreads();   // everyone done reading tile + shWd

        // relu + store transposed
        unsigned long long av[4] = {acc0, acc1, acc2, acc3};
        #pragma unroll
        for (int t = 0; t < 4; t++) {
            float lo, hi;
            asm("mov.b64 {%0, %1}, %2;" : "=f"(lo), "=f"(hi) : "l"(av[t]));
            *(float2*)&tile[(kb + t) * TS + 2 * ep] =
                make_float2(fmaxf(lo, 0.f), fmaxf(hi, 0.f));
        }
        __syncthreads();
    }

    // sum over this block's events -> atomic into g_gsum
    if (tid < D) {
        float s = 0.f;
        #pragma unroll
        for (int e = 0; e < EVB; e++) s += tile[tid * TS + e];
        atomicAdd(&g_gsum[tid], s);
    }

    // ---- last-block ticket: rho2 + output ----
    __threadfence();
    __syncthreads();
    if (tid == 0) {
        int old = atomicAdd(&g_cnt, 1);
        s_last = (old == (int)gridDim.x - 1);
    }
    __syncthreads();

    if (s_last) {
        if (tid < D) sf0[tid] = __ldcg(&g_gsum[tid]);
        __syncthreads();
        if (tid < D) {
            float a = r2b0[tid];
            #pragma unroll
            for (int j = 0; j < D; j++) a += sf0[j] * r2w0[j * D + tid];
            sf1[tid] = fmaxf(a, 0.f);
        }
        __syncthreads();
        if (tid < D) {
            float a = r2b1[tid];
            #pragma unroll
            for (int j = 0; j < D; j++) a += sf1[j] * r2w1[j * D + tid];
            sf2[tid] = fmaxf(a, 0.f);
        }
        __syncthreads();
        if (tid < 10) {
            float a = o2b[tid];
            #pragma unroll
            for (int j = 0; j < D; j++) a += sf2[j] * o2w[j * 10 + tid];
            out[tid] = a;
        }
        if (tid == 0) g_cnt = 0;   // self-reset for next replay
    }
}

// ---------------- launch ----------------
extern "C" void kernel_launch(void* const* d_in, const int* in_sizes, int n_in,
                              void* d_out, int out_size)
{
    const float* x    = (const float*)d_in[0];
    const int*   seg  = (const int*)  d_in[1];
    const float* p1w0 = (const float*)d_in[2];
    const float* p1b0 = (const float*)d_in[3];
    const float* p1w1 = (const float*)d_in[4];
    const float* p1b1 = (const float*)d_in[5];
    const float* r1w0 = (const float*)d_in[6];
    const float* r1b0 = (const float*)d_in[7];
    const float* r1w1 = (const float*)d_in[8];
    const float* r1b1 = (const float*)d_in[9];
    const float* o1w  = (const float*)d_in[10];
    const float* o1b  = (const float*)d_in[11];
    const float* p2w0 = (const float*)d_in[12];
    const float* p2b0 = (const float*)d_in[13];
    const float* p2w1 = (const float*)d_in[14];
    const float* p2b1 = (const float*)d_in[15];
    const float* r2w0 = (const float*)d_in[16];
    const float* r2b0 = (const float*)d_in[17];
    const float* r2w1 = (const float*)d_in[18];
    const float* r2b1 = (const float*)d_in[19];
    const float* o2w  = (const float*)d_in[20];
    const float* o2b  = (const float*)d_in[21];
    const int n = in_sizes[0];

    void* zp = nullptr;
    cudaGetSymbolAddress(&zp, g_zero);
    cudaMemsetAsync(zp, 0, sizeof(float) * (2 * E_NUM + D + E_NUM * D));

    k_stage1<<<S1_BLOCKS, 256>>>(x, seg, n, p1w0, p1b0, p1w1, p1b1, r1w0);
    k_events_final<<<EV_BLOCKS, 256>>>(r1w0, r1b0, r1w1, r1b1, o1w, o1b,
                                       p2w0, p2b0, p2w1, p2b1,
                                       r2w0, r2b0, r2w1, r2b1,
                                       o2w, o2b, (float*)d_out);
}